// round 2
// baseline (speedup 1.0000x reference)
#include <cuda_runtime.h>
#include <math.h>

// ============================================================================
// DoRA-LoRA linear, algebraically collapsed:
//   out = x @ (diag(mag/rownorm(W+2BA)) * (W + 2*B@A))^T
// Kernel 1: build scaled effective weight (tiny).
// Kernel 2: fp32 SGEMM 32768x1024x1024 using packed fma.rn.f32x2.
// ============================================================================

#define SCALING 2.0f          // alpha/rank = 32/16
#define MAX_DOUT 1024
#define MAX_DIN  1024

__device__ float g_Wsc[MAX_DOUT * MAX_DIN];   // scratch: scaled effective weight

// ---------------------------------------------------------------------------
// Prep: one block per output row o.
//   w_eff[o,d] = W[o,d] + 2 * sum_r b[o,r]*a[r,d]
//   Wsc[o,d]   = (mag[o] / ||w_eff[o,:]||) * w_eff[o,d]
// ---------------------------------------------------------------------------
__global__ void prep_kernel(const float* __restrict__ weight,
                            const float* __restrict__ a_w,
                            const float* __restrict__ b_w,
                            const float* __restrict__ magnitude,
                            int D_IN, int R) {
    int o = blockIdx.x;
    int tid = threadIdx.x;

    __shared__ float bs[32];
    if (tid < R) bs[tid] = b_w[o * R + tid];
    __syncthreads();

    float sumsq = 0.f;
    for (int d = tid; d < D_IN; d += blockDim.x) {
        float corr = 0.f;
        #pragma unroll 16
        for (int r = 0; r < R; ++r) corr += bs[r] * a_w[r * D_IN + d];
        float w = weight[o * D_IN + d] + SCALING * corr;
        g_Wsc[o * D_IN + d] = w;
        sumsq += w * w;
    }

    // block reduction of sumsq
    __shared__ float red[32];
    #pragma unroll
    for (int off = 16; off > 0; off >>= 1)
        sumsq += __shfl_down_sync(0xffffffffu, sumsq, off);
    if ((tid & 31) == 0) red[tid >> 5] = sumsq;
    __syncthreads();
    if (tid < 32) {
        float v = (tid < (blockDim.x + 31) / 32) ? red[tid] : 0.f;
        #pragma unroll
        for (int off = 16; off > 0; off >>= 1)
            v += __shfl_down_sync(0xffffffffu, v, off);
        if (tid == 0) red[0] = v;
    }
    __syncthreads();

    float scale = magnitude[o] / sqrtf(red[0]);
    for (int d = tid; d < D_IN; d += blockDim.x)
        g_Wsc[o * D_IN + d] *= scale;
}

// ---------------------------------------------------------------------------
// SGEMM: out[M,N] = X[M,K] @ Wsc[N,K]^T, fp32, packed f32x2 FMA.
// Tiles: BM=BN=128, BK=8; 256 threads; each thread computes 8x8 (as 8m x 4
// n-pairs). A is stored DUPLICATED in smem (each value twice) so the packed
// multiplicand dup costs zero instructions in the inner loop.
// ---------------------------------------------------------------------------
#define BM 128
#define BN 128
#define BK 8

typedef unsigned long long u64;

__device__ __forceinline__ u64 fma2(u64 a, u64 b, u64 c) {
    u64 d;
    asm("fma.rn.f32x2 %0, %1, %2, %3;" : "=l"(d) : "l"(a), "l"(b), "l"(c));
    return d;
}
__device__ __forceinline__ void unpack2(u64 v, float& lo, float& hi) {
    asm("mov.b64 {%0, %1}, %2;" : "=f"(lo), "=f"(hi) : "l"(v));
}

__global__ void __launch_bounds__(256, 2)
gemm_f32x2_kernel(const float* __restrict__ X,
                  float* __restrict__ out,
                  int M, int N, int K) {
    __shared__ float As[2][BK][2 * BM];   // duplicated A: 16 KB
    __shared__ float Bs[2][BK][BN];       // 8 KB

    int tid = threadIdx.x;
    int tx = tid & 15;        // n-direction (16)
    int ty = tid >> 4;        // m-direction (16)

    int m0 = blockIdx.y * BM;
    int n0 = blockIdx.x * BN;

    // global load mapping: each thread one float4 of A and of B per tile
    int lrow = tid >> 1;              // 0..127
    int lc4  = (tid & 1) * 4;         // 0 or 4
    const float* Aptr = X     + (size_t)(m0 + lrow) * K + lc4;
    const float* Bptr = g_Wsc + (size_t)(n0 + lrow) * K + lc4;

    u64 acc[8][4];
    #pragma unroll
    for (int i = 0; i < 8; ++i)
        #pragma unroll
        for (int j = 0; j < 4; ++j) acc[i][j] = 0ull;

    int nt = K / BK;

    // load tile 0
    float4 ra = *(const float4*)Aptr;
    float4 rb = *(const float4*)Bptr;
    {
        float va[4] = {ra.x, ra.y, ra.z, ra.w};
        float vb[4] = {rb.x, rb.y, rb.z, rb.w};
        #pragma unroll
        for (int i = 0; i < 4; ++i) {
            float2 d2 = make_float2(va[i], va[i]);
            *(float2*)&As[0][lc4 + i][2 * lrow] = d2;
            Bs[0][lc4 + i][lrow] = vb[i];
        }
    }
    __syncthreads();

    for (int t = 0; t < nt; ++t) {
        int buf = t & 1;
        if (t + 1 < nt) {
            ra = *(const float4*)(Aptr + (t + 1) * BK);
            rb = *(const float4*)(Bptr + (t + 1) * BK);
        }

        #pragma unroll
        for (int kk = 0; kk < BK; ++kk) {
            const u64* Ak = (const u64*)&As[buf][kk][0];  // 128 u64, idx = m
            const u64* Bk = (const u64*)&Bs[buf][kk][0];  // 64 u64, idx = n/2

            ulonglong2 aA = *(const ulonglong2*)(Ak + (ty << 2));
            ulonglong2 aB = *(const ulonglong2*)(Ak + (ty << 2) + 2);
            ulonglong2 aC = *(const ulonglong2*)(Ak + 64 + (ty << 2));
            ulonglong2 aD = *(const ulonglong2*)(Ak + 64 + (ty << 2) + 2);
            ulonglong2 b01 = *(const ulonglong2*)(Bk + (tx << 1));
            ulonglong2 b23 = *(const ulonglong2*)(Bk + 32 + (tx << 1));

            u64 ad[8] = {aA.x, aA.y, aB.x, aB.y, aC.x, aC.y, aD.x, aD.y};
            u64 bp[4] = {b01.x, b01.y, b23.x, b23.y};

            #pragma unroll
            for (int mi = 0; mi < 8; ++mi)
                #pragma unroll
                for (int pj = 0; pj < 4; ++pj)
                    acc[mi][pj] = fma2(ad[mi], bp[pj], acc[mi][pj]);
        }

        if (t + 1 < nt) {
            int nbuf = (t + 1) & 1;
            float va[4] = {ra.x, ra.y, ra.z, ra.w};
            float vb[4] = {rb.x, rb.y, rb.z, rb.w};
            #pragma unroll
            for (int i = 0; i < 4; ++i) {
                float2 d2 = make_float2(va[i], va[i]);
                *(float2*)&As[nbuf][lc4 + i][2 * lrow] = d2;
                Bs[nbuf][lc4 + i][lrow] = vb[i];
            }
            __syncthreads();
        }
    }

    // epilogue: each thread owns rows {ty*4+i, 64+ty*4+i}, cols {tx*4..+3, 64+tx*4..+3}
    #pragma unroll
    for (int mi = 0; mi < 8; ++mi) {
        int mloc = (mi < 4) ? (ty * 4 + mi) : (64 + ty * 4 + (mi - 4));
        float* orow = out + (size_t)(m0 + mloc) * N + n0;
        float4 v0, v1;
        unpack2(acc[mi][0], v0.x, v0.y);
        unpack2(acc[mi][1], v0.z, v0.w);
        unpack2(acc[mi][2], v1.x, v1.y);
        unpack2(acc[mi][3], v1.z, v1.w);
        *(float4*)(orow + tx * 4)      = v0;
        *(float4*)(orow + 64 + tx * 4) = v1;
    }
}

// ---------------------------------------------------------------------------
extern "C" void kernel_launch(void* const* d_in, const int* in_sizes, int n_in,
                              void* d_out, int out_size) {
    const float* x        = (const float*)d_in[0];
    const float* weight   = (const float*)d_in[1];
    const float* a_w      = (const float*)d_in[2];
    const float* b_w      = (const float*)d_in[3];
    const float* mag      = (const float*)d_in[4];
    float* out            = (float*)d_out;

    int D_OUT = in_sizes[4];              // magnitude: (1, D_OUT)
    int R     = in_sizes[3] / D_OUT;      // b_w: (D_OUT, R)
    int D_IN  = in_sizes[2] / R;          // a_w: (R, D_IN)
    int M     = in_sizes[0] / D_IN;       // x: (B*S, D_IN)

    prep_kernel<<<D_OUT, 256>>>(weight, a_w, b_w, mag, D_IN, R);

    dim3 grid(D_OUT / BN, M / BM);
    gemm_f32x2_kernel<<<grid, 256>>>(x, out, M, D_OUT, D_IN);
}

// round 4
// speedup vs baseline: 2.0180x; 2.0180x over previous
#include <cuda_runtime.h>
#include <cuda_bf16.h>
#include <stdint.h>
#include <math.h>

#define SCALING 2.0f
#define MAXM 32768
#define MAXD 1024

// Static scratch (allocation-free per harness rules)
__device__ __nv_bfloat16 g_Xhi[(size_t)MAXM * MAXD];
__device__ __nv_bfloat16 g_Xlo[(size_t)MAXM * MAXD];
__device__ __nv_bfloat16 g_Whi[(size_t)MAXD * MAXD];
__device__ __nv_bfloat16 g_Wlo[(size_t)MAXD * MAXD];

// ============================ Prep ============================
// One block per output row o: w_eff = W[o,:] + 2*b[o,:]@A; scale mag/||w_eff||;
// split into bf16 hi/lo.
__global__ void prep_kernel(const float* __restrict__ weight,
                            const float* __restrict__ a_w,
                            const float* __restrict__ b_w,
                            const float* __restrict__ magnitude,
                            int D_IN, int R) {
    int o = blockIdx.x;
    int tid = threadIdx.x;
    __shared__ float bs[32];
    __shared__ float red[33];
    if (tid < R) bs[tid] = b_w[o * R + tid];
    __syncthreads();

    float wv[8];
    float sumsq = 0.f;
    int cnt = 0;
    for (int d = tid; d < D_IN; d += 256, ++cnt) {
        float corr = 0.f;
        #pragma unroll 16
        for (int r = 0; r < R; ++r) corr += bs[r] * a_w[(size_t)r * D_IN + d];
        float w = weight[(size_t)o * D_IN + d] + SCALING * corr;
        wv[cnt] = w;
        sumsq += w * w;
    }
    #pragma unroll
    for (int off = 16; off; off >>= 1)
        sumsq += __shfl_down_sync(0xffffffffu, sumsq, off);
    if ((tid & 31) == 0) red[tid >> 5] = sumsq;
    __syncthreads();
    if (tid < 32) {
        float v = (tid < 8) ? red[tid] : 0.f;
        #pragma unroll
        for (int off = 16; off; off >>= 1)
            v += __shfl_down_sync(0xffffffffu, v, off);
        if (tid == 0) red[32] = v;
    }
    __syncthreads();
    float scale = magnitude[o] * rsqrtf(red[32]);
    cnt = 0;
    for (int d = tid; d < D_IN; d += 256, ++cnt) {
        float w = wv[cnt] * scale;
        __nv_bfloat16 hi = __float2bfloat16(w);
        __nv_bfloat16 lo = __float2bfloat16(w - __bfloat162float(hi));
        g_Whi[(size_t)o * D_IN + d] = hi;
        g_Wlo[(size_t)o * D_IN + d] = lo;
    }
}

__global__ void split_x_kernel(const float* __restrict__ x, size_t n4) {
    size_t i = (size_t)blockIdx.x * blockDim.x + threadIdx.x;
    size_t stride = (size_t)gridDim.x * blockDim.x;
    const float4* x4 = (const float4*)x;
    __nv_bfloat162* xh2 = (__nv_bfloat162*)g_Xhi;
    __nv_bfloat162* xl2 = (__nv_bfloat162*)g_Xlo;
    for (; i < n4; i += stride) {
        float4 v = x4[i];
        __nv_bfloat16 h0 = __float2bfloat16(v.x);
        __nv_bfloat16 h1 = __float2bfloat16(v.y);
        __nv_bfloat16 h2 = __float2bfloat16(v.z);
        __nv_bfloat16 h3 = __float2bfloat16(v.w);
        __nv_bfloat16 l0 = __float2bfloat16(v.x - __bfloat162float(h0));
        __nv_bfloat16 l1 = __float2bfloat16(v.y - __bfloat162float(h1));
        __nv_bfloat16 l2 = __float2bfloat16(v.z - __bfloat162float(h2));
        __nv_bfloat16 l3 = __float2bfloat16(v.w - __bfloat162float(h3));
        xh2[2 * i]     = __halves2bfloat162(h0, h1);
        xh2[2 * i + 1] = __halves2bfloat162(h2, h3);
        xl2[2 * i]     = __halves2bfloat162(l0, l1);
        xl2[2 * i + 1] = __halves2bfloat162(l2, l3);
    }
}

// ============================ HMMA GEMM ============================
// out[M,N] = sum over 3 terms of A_t[M,K] @ B_t[N,K]^T, bf16 in, fp32 accum.
// CTA tile 128(M) x 256(N); 8 warps, warp tile 64x64; K-chunk 32; 4-stage
// cp.async pipeline. smem tiles swizzled (16B-chunk XOR (row>>1)&3) for
// conflict-free ldmatrix.
#define BM 128
#define BN 256
#define BK 32
#define STAGES 4
#define A_BYTES (BM * 64)          // 8 KB (64B per row = 32 bf16)
#define B_BYTES (BN * 64)          // 16 KB
#define STAGE_BYTES (A_BYTES + B_BYTES)
#define SMEM_TOTAL (STAGES * STAGE_BYTES)

__device__ __forceinline__ uint32_t smem_u32(const void* p) {
    uint32_t a;
    asm("{ .reg .u64 t; cvta.to.shared.u64 t, %1; cvt.u32.u64 %0, t; }"
        : "=r"(a) : "l"(p));
    return a;
}
__device__ __forceinline__ void cp16(uint32_t dst, const void* src) {
    asm volatile("cp.async.cg.shared.global [%0], [%1], 16;"
                 :: "r"(dst), "l"(src) : "memory");
}
__device__ __forceinline__ void cp_commit() {
    asm volatile("cp.async.commit_group;" ::: "memory");
}
template <int N_>
__device__ __forceinline__ void cp_wait() {
    asm volatile("cp.async.wait_group %0;" :: "n"(N_) : "memory");
}
__device__ __forceinline__ void ldsm_x4(uint32_t& r0, uint32_t& r1,
                                        uint32_t& r2, uint32_t& r3, uint32_t a) {
    asm volatile("ldmatrix.sync.aligned.m8n8.x4.shared.b16 {%0,%1,%2,%3}, [%4];"
                 : "=r"(r0), "=r"(r1), "=r"(r2), "=r"(r3) : "r"(a));
}
__device__ __forceinline__ void mma16816(float* c, const uint32_t* a,
                                         uint32_t b0, uint32_t b1) {
    asm volatile(
        "mma.sync.aligned.m16n8k16.row.col.f32.bf16.bf16.f32 "
        "{%0,%1,%2,%3}, {%4,%5,%6,%7}, {%8,%9}, {%0,%1,%2,%3};"
        : "+f"(c[0]), "+f"(c[1]), "+f"(c[2]), "+f"(c[3])
        : "r"(a[0]), "r"(a[1]), "r"(a[2]), "r"(a[3]), "r"(b0), "r"(b1));
}

// swizzled byte offset within a tile: row has 4 x 16B chunks
__device__ __forceinline__ uint32_t sw_off(int row, int ch) {
    return (uint32_t)(row * 64 + ((ch ^ ((row >> 1) & 3)) * 16));
}

__global__ void __launch_bounds__(256, 1)
gemm_hmma_kernel(float* __restrict__ out, int M, int N, int K) {
    extern __shared__ char smem[];
    const uint32_t sb = smem_u32(smem);
    const int tid = threadIdx.x;
    const int wid = tid >> 5;
    const int lane = tid & 31;
    const int wm = (wid & 1) * 64;        // warp m-offset in tile
    const int wn = (wid >> 1) * 64;       // warp n-offset in tile
    const int m0 = blockIdx.y * BM;
    const int n0 = blockIdx.x * BN;

    const __nv_bfloat16* Asrc[3] = { g_Xhi, g_Xlo, g_Xhi };
    const __nv_bfloat16* Bsrc[3] = { g_Whi, g_Whi, g_Wlo };

    const int nchunk = 3 * (K / BK);      // 96

    // ---- async load of one chunk into a stage ----
    auto issue = [&](int c, int stage) {
        int term = c % 3;
        int kofs = (c / 3) * BK;
        const __nv_bfloat16* As = Asrc[term];
        const __nv_bfloat16* Bs = Bsrc[term];
        uint32_t abase = sb + stage * STAGE_BYTES;
        uint32_t bbase = abase + A_BYTES;
        // A: 512 16B units, 2 per thread
        #pragma unroll
        for (int j = 0; j < 2; ++j) {
            int u = tid + 256 * j;
            int row = u >> 2, ch = u & 3;
            cp16(abase + sw_off(row, ch),
                 As + (size_t)(m0 + row) * K + kofs + ch * 8);
        }
        // B: 1024 16B units, 4 per thread
        #pragma unroll
        for (int j = 0; j < 4; ++j) {
            int u = tid + 256 * j;
            int row = u >> 2, ch = u & 3;
            cp16(bbase + sw_off(row, ch),
                 Bs + (size_t)(n0 + row) * K + kofs + ch * 8);
        }
        cp_commit();
    };

    float acc[4][8][4];
    #pragma unroll
    for (int i = 0; i < 4; ++i)
        #pragma unroll
        for (int j = 0; j < 8; ++j)
            #pragma unroll
            for (int q = 0; q < 4; ++q) acc[i][j][q] = 0.f;

    issue(0, 0); issue(1, 1); issue(2, 2);

    for (int c = 0; c < nchunk; ++c) {
        cp_wait<STAGES - 2>();
        __syncthreads();
        if (c + 3 < nchunk) issue(c + 3, (c + 3) % STAGES);

        int stage = c % STAGES;
        uint32_t abase = sb + stage * STAGE_BYTES;
        uint32_t bbase = abase + A_BYTES;

        #pragma unroll
        for (int h = 0; h < 2; ++h) {      // two k16 halves of the K32 chunk
            // A frags: 4 x (16x16)
            uint32_t afr[4][4];
            #pragma unroll
            for (int mf = 0; mf < 4; ++mf) {
                int row = wm + mf * 16 + (lane & 15);
                int ch = h * 2 + (lane >> 4);
                ldsm_x4(afr[mf][0], afr[mf][1], afr[mf][2], afr[mf][3],
                        abase + sw_off(row, ch));
            }
            // B frags: 4 x (16n x 16k) -> 8 n8 frags
            uint32_t bfr[4][4];
            #pragma unroll
            for (int p = 0; p < 4; ++p) {
                int row = wn + p * 16 + (lane & 15);
                int ch = h * 2 + (lane >> 4);
                ldsm_x4(bfr[p][0], bfr[p][1], bfr[p][2], bfr[p][3],
                        bbase + sw_off(row, ch));
            }
            #pragma unroll
            for (int mf = 0; mf < 4; ++mf)
                #pragma unroll
                for (int p = 0; p < 4; ++p) {
                    mma16816(acc[mf][2 * p],     afr[mf], bfr[p][0], bfr[p][2]);
                    mma16816(acc[mf][2 * p + 1], afr[mf], bfr[p][1], bfr[p][3]);
                }
        }
    }
    cp_wait<0>();

    // Epilogue: direct float2 stores from fragments
    #pragma unroll
    for (int mf = 0; mf < 4; ++mf) {
        int rbase = m0 + wm + mf * 16 + (lane >> 2);
        #pragma unroll
        for (int nf = 0; nf < 8; ++nf) {
            int cbase = n0 + wn + nf * 8 + (lane & 3) * 2;
            float* p0 = out + (size_t)rbase * N + cbase;
            float* p1 = out + (size_t)(rbase + 8) * N + cbase;
            *(float2*)p0 = make_float2(acc[mf][nf][0], acc[mf][nf][1]);
            *(float2*)p1 = make_float2(acc[mf][nf][2], acc[mf][nf][3]);
        }
    }
}

// ============================ launch ============================
extern "C" void kernel_launch(void* const* d_in, const int* in_sizes, int n_in,
                              void* d_out, int out_size) {
    const float* x      = (const float*)d_in[0];
    const float* weight = (const float*)d_in[1];
    const float* a_w    = (const float*)d_in[2];
    const float* b_w    = (const float*)d_in[3];
    const float* mag    = (const float*)d_in[4];
    float* out          = (float*)d_out;

    int D_OUT = in_sizes[4];              // magnitude: (1, D_OUT)
    int R     = in_sizes[3] / D_OUT;      // b_w: (D_OUT, R)
    int D_IN  = in_sizes[2] / R;          // a_w: (R, D_IN)
    int M     = in_sizes[0] / D_IN;       // x: (B*S, D_IN)

    cudaFuncSetAttribute(gemm_hmma_kernel,
                         cudaFuncAttributeMaxDynamicSharedMemorySize, SMEM_TOTAL);

    prep_kernel<<<D_OUT, 256>>>(weight, a_w, b_w, mag, D_IN, R);
    size_t n4 = ((size_t)M * D_IN) / 4;
    split_x_kernel<<<1024, 256>>>(x, n4);

    dim3 grid(D_OUT / BN, M / BM);
    gemm_hmma_kernel<<<grid, 256, SMEM_TOTAL>>>(out, M, D_OUT, D_IN);
}

// round 5
// speedup vs baseline: 2.2757x; 1.1277x over previous
#include <cuda_runtime.h>
#include <cuda_bf16.h>
#include <stdint.h>
#include <math.h>

#define SCALING 2.0f
#define MAXM 32768
#define MAXD 1024

// Static scratch (allocation-free per harness rules)
__device__ __nv_bfloat16 g_Xhi[(size_t)MAXM * MAXD];
__device__ __nv_bfloat16 g_Xlo[(size_t)MAXM * MAXD];
__device__ __nv_bfloat16 g_Whi[(size_t)MAXD * MAXD];
__device__ __nv_bfloat16 g_Wlo[(size_t)MAXD * MAXD];

// ============================ Prep ============================
__global__ void prep_kernel(const float* __restrict__ weight,
                            const float* __restrict__ a_w,
                            const float* __restrict__ b_w,
                            const float* __restrict__ magnitude,
                            int D_IN, int R) {
    int o = blockIdx.x;
    int tid = threadIdx.x;
    __shared__ float bs[32];
    __shared__ float red[33];
    if (tid < R) bs[tid] = b_w[o * R + tid];
    __syncthreads();

    float wv[8];
    float sumsq = 0.f;
    int cnt = 0;
    for (int d = tid; d < D_IN; d += 256, ++cnt) {
        float corr = 0.f;
        #pragma unroll 16
        for (int r = 0; r < R; ++r) corr += bs[r] * a_w[(size_t)r * D_IN + d];
        float w = weight[(size_t)o * D_IN + d] + SCALING * corr;
        wv[cnt] = w;
        sumsq += w * w;
    }
    #pragma unroll
    for (int off = 16; off; off >>= 1)
        sumsq += __shfl_down_sync(0xffffffffu, sumsq, off);
    if ((tid & 31) == 0) red[tid >> 5] = sumsq;
    __syncthreads();
    if (tid < 32) {
        float v = (tid < 8) ? red[tid] : 0.f;
        #pragma unroll
        for (int off = 16; off; off >>= 1)
            v += __shfl_down_sync(0xffffffffu, v, off);
        if (tid == 0) red[32] = v;
    }
    __syncthreads();
    float scale = magnitude[o] * rsqrtf(red[32]);
    cnt = 0;
    for (int d = tid; d < D_IN; d += 256, ++cnt) {
        float w = wv[cnt] * scale;
        __nv_bfloat16 hi = __float2bfloat16(w);
        __nv_bfloat16 lo = __float2bfloat16(w - __bfloat162float(hi));
        g_Whi[(size_t)o * D_IN + d] = hi;
        g_Wlo[(size_t)o * D_IN + d] = lo;
    }
}

__global__ void split_x_kernel(const float* __restrict__ x, size_t n4) {
    size_t i = (size_t)blockIdx.x * blockDim.x + threadIdx.x;
    size_t stride = (size_t)gridDim.x * blockDim.x;
    const float4* x4 = (const float4*)x;
    __nv_bfloat162* xh2 = (__nv_bfloat162*)g_Xhi;
    __nv_bfloat162* xl2 = (__nv_bfloat162*)g_Xlo;
    for (; i < n4; i += stride) {
        float4 v = x4[i];
        __nv_bfloat16 h0 = __float2bfloat16(v.x);
        __nv_bfloat16 h1 = __float2bfloat16(v.y);
        __nv_bfloat16 h2 = __float2bfloat16(v.z);
        __nv_bfloat16 h3 = __float2bfloat16(v.w);
        __nv_bfloat16 l0 = __float2bfloat16(v.x - __bfloat162float(h0));
        __nv_bfloat16 l1 = __float2bfloat16(v.y - __bfloat162float(h1));
        __nv_bfloat16 l2 = __float2bfloat16(v.z - __bfloat162float(h2));
        __nv_bfloat16 l3 = __float2bfloat16(v.w - __bfloat162float(h3));
        xh2[2 * i]     = __halves2bfloat162(h0, h1);
        xh2[2 * i + 1] = __halves2bfloat162(h2, h3);
        xl2[2 * i]     = __halves2bfloat162(l0, l1);
        xl2[2 * i + 1] = __halves2bfloat162(l2, l3);
    }
}

// ============================ HMMA GEMM (term-fused) ============================
// out = Xhi@Whi^T + Xlo@Whi^T + Xhi@Wlo^T (all fp32 accum into one acc set).
// CTA tile 128(M) x 256(N); 8 warps (2m x 4n), warp tile 64x64; K-chunk 32.
// Per chunk: load Ahi/Alo/Bhi/Blo tiles once, run all 3 terms (96 mma / 16 ldsm
// per h-half pair). 4-stage cp.async pipeline, 48KB/stage.
#define BM 128
#define BN 256
#define BK 32
#define STAGES 4
#define AT_BYTES (BM * 64)            // 8 KB per A tile (64B/row)
#define BT_BYTES (BN * 64)            // 16 KB per B tile
#define STAGE_BYTES (2 * AT_BYTES + 2 * BT_BYTES)   // 48 KB
#define SMEM_TOTAL (STAGES * STAGE_BYTES)           // 192 KB
#define AHI_OFF 0
#define ALO_OFF AT_BYTES
#define BHI_OFF (2 * AT_BYTES)
#define BLO_OFF (2 * AT_BYTES + BT_BYTES)

__device__ __forceinline__ uint32_t smem_u32(const void* p) {
    uint32_t a;
    asm("{ .reg .u64 t; cvta.to.shared.u64 t, %1; cvt.u32.u64 %0, t; }"
        : "=r"(a) : "l"(p));
    return a;
}
__device__ __forceinline__ void cp16(uint32_t dst, const void* src) {
    asm volatile("cp.async.cg.shared.global [%0], [%1], 16;"
                 :: "r"(dst), "l"(src) : "memory");
}
__device__ __forceinline__ void cp_commit() {
    asm volatile("cp.async.commit_group;" ::: "memory");
}
template <int N_>
__device__ __forceinline__ void cp_wait() {
    asm volatile("cp.async.wait_group %0;" :: "n"(N_) : "memory");
}
__device__ __forceinline__ void ldsm_x4(uint32_t& r0, uint32_t& r1,
                                        uint32_t& r2, uint32_t& r3, uint32_t a) {
    asm volatile("ldmatrix.sync.aligned.m8n8.x4.shared.b16 {%0,%1,%2,%3}, [%4];"
                 : "=r"(r0), "=r"(r1), "=r"(r2), "=r"(r3) : "r"(a));
}
__device__ __forceinline__ void mma16816(float* c, const uint32_t* a,
                                         uint32_t b0, uint32_t b1) {
    asm volatile(
        "mma.sync.aligned.m16n8k16.row.col.f32.bf16.bf16.f32 "
        "{%0,%1,%2,%3}, {%4,%5,%6,%7}, {%8,%9}, {%0,%1,%2,%3};"
        : "+f"(c[0]), "+f"(c[1]), "+f"(c[2]), "+f"(c[3])
        : "r"(a[0]), "r"(a[1]), "r"(a[2]), "r"(a[3]), "r"(b0), "r"(b1));
}
// swizzled byte offset within a tile: row = 4 x 16B chunks, XOR by (row>>1)&3
__device__ __forceinline__ uint32_t sw_off(int row, int ch) {
    return (uint32_t)(row * 64 + ((ch ^ ((row >> 1) & 3)) * 16));
}

__global__ void __launch_bounds__(256, 1)
gemm_hmma_kernel(float* __restrict__ out, int M, int N, int K) {
    extern __shared__ char smem[];
    const uint32_t sb = smem_u32(smem);
    const int tid = threadIdx.x;
    const int wid = tid >> 5;
    const int lane = tid & 31;
    const int wm = (wid & 1) * 64;
    const int wn = (wid >> 1) * 64;
    const int m0 = blockIdx.y * BM;
    const int n0 = blockIdx.x * BN;

    const int nchunk = K / BK;   // 32

    auto issue = [&](int c, int stage) {
        int kofs = c * BK;
        uint32_t base = sb + stage * STAGE_BYTES;
        // A hi/lo: 512 16B units each, 2 per thread
        #pragma unroll
        for (int j = 0; j < 2; ++j) {
            int u = tid + 256 * j;
            int row = u >> 2, ch = u & 3;
            size_t gofs = (size_t)(m0 + row) * K + kofs + ch * 8;
            cp16(base + AHI_OFF + sw_off(row, ch), g_Xhi + gofs);
            cp16(base + ALO_OFF + sw_off(row, ch), g_Xlo + gofs);
        }
        // B hi/lo: 1024 16B units each, 4 per thread
        #pragma unroll
        for (int j = 0; j < 4; ++j) {
            int u = tid + 256 * j;
            int row = u >> 2, ch = u & 3;
            size_t gofs = (size_t)(n0 + row) * K + kofs + ch * 8;
            cp16(base + BHI_OFF + sw_off(row, ch), g_Whi + gofs);
            cp16(base + BLO_OFF + sw_off(row, ch), g_Wlo + gofs);
        }
        cp_commit();
    };

    float acc[4][8][4];
    #pragma unroll
    for (int i = 0; i < 4; ++i)
        #pragma unroll
        for (int j = 0; j < 8; ++j)
            #pragma unroll
            for (int q = 0; q < 4; ++q) acc[i][j][q] = 0.f;

    issue(0, 0); issue(1, 1); issue(2, 2);

    for (int c = 0; c < nchunk; ++c) {
        cp_wait<STAGES - 2>();
        __syncthreads();
        if (c + 3 < nchunk) issue(c + 3, (c + 3) % STAGES);

        uint32_t base = sb + (c % STAGES) * STAGE_BYTES;

        #pragma unroll
        for (int h = 0; h < 2; ++h) {
            const int ch = h * 2 + (lane >> 4);
            uint32_t ah[4][4], al[4][4], bh[4][4], bl[4][4];
            #pragma unroll
            for (int mf = 0; mf < 4; ++mf) {
                int row = wm + mf * 16 + (lane & 15);
                uint32_t so = sw_off(row, ch);
                ldsm_x4(ah[mf][0], ah[mf][1], ah[mf][2], ah[mf][3],
                        base + AHI_OFF + so);
                ldsm_x4(al[mf][0], al[mf][1], al[mf][2], al[mf][3],
                        base + ALO_OFF + so);
            }
            #pragma unroll
            for (int p = 0; p < 4; ++p) {
                int row = wn + p * 16 + (lane & 15);
                uint32_t so = sw_off(row, ch);
                ldsm_x4(bh[p][0], bh[p][1], bh[p][2], bh[p][3],
                        base + BHI_OFF + so);
                ldsm_x4(bl[p][0], bl[p][1], bl[p][2], bl[p][3],
                        base + BLO_OFF + so);
            }
            #pragma unroll
            for (int mf = 0; mf < 4; ++mf)
                #pragma unroll
                for (int p = 0; p < 4; ++p) {
                    // term 0: hi * hi
                    mma16816(acc[mf][2 * p],     ah[mf], bh[p][0], bh[p][2]);
                    mma16816(acc[mf][2 * p + 1], ah[mf], bh[p][1], bh[p][3]);
                    // term 1: lo * hi
                    mma16816(acc[mf][2 * p],     al[mf], bh[p][0], bh[p][2]);
                    mma16816(acc[mf][2 * p + 1], al[mf], bh[p][1], bh[p][3]);
                    // term 2: hi * lo
                    mma16816(acc[mf][2 * p],     ah[mf], bl[p][0], bl[p][2]);
                    mma16816(acc[mf][2 * p + 1], ah[mf], bl[p][1], bl[p][3]);
                }
        }
    }
    cp_wait<0>();

    // Epilogue: direct float2 stores from fragments
    #pragma unroll
    for (int mf = 0; mf < 4; ++mf) {
        int rbase = m0 + wm + mf * 16 + (lane >> 2);
        #pragma unroll
        for (int nf = 0; nf < 8; ++nf) {
            int cbase = n0 + wn + nf * 8 + (lane & 3) * 2;
            float* p0 = out + (size_t)rbase * N + cbase;
            float* p1 = out + (size_t)(rbase + 8) * N + cbase;
            *(float2*)p0 = make_float2(acc[mf][nf][0], acc[mf][nf][1]);
            *(float2*)p1 = make_float2(acc[mf][nf][2], acc[mf][nf][3]);
        }
    }
}

// ============================ launch ============================
extern "C" void kernel_launch(void* const* d_in, const int* in_sizes, int n_in,
                              void* d_out, int out_size) {
    const float* x      = (const float*)d_in[0];
    const float* weight = (const float*)d_in[1];
    const float* a_w    = (const float*)d_in[2];
    const float* b_w    = (const float*)d_in[3];
    const float* mag    = (const float*)d_in[4];
    float* out          = (float*)d_out;

    int D_OUT = in_sizes[4];
    int R     = in_sizes[3] / D_OUT;
    int D_IN  = in_sizes[2] / R;
    int M     = in_sizes[0] / D_IN;

    cudaFuncSetAttribute(gemm_hmma_kernel,
                         cudaFuncAttributeMaxDynamicSharedMemorySize, SMEM_TOTAL);

    prep_kernel<<<D_OUT, 256>>>(weight, a_w, b_w, mag, D_IN, R);
    size_t n4 = ((size_t)M * D_IN) / 4;
    split_x_kernel<<<1024, 256>>>(x, n4);

    dim3 grid(D_OUT / BN, M / BM);
    gemm_hmma_kernel<<<grid, 256, SMEM_TOTAL>>>(out, M, D_OUT, D_IN);
}

// round 6
// speedup vs baseline: 2.4069x; 1.0576x over previous
#include <cuda_runtime.h>
#include <cuda_bf16.h>
#include <stdint.h>
#include <math.h>

#define SCALING 2.0f
#define MAXM 32768
#define MAXD 1024

// Static scratch (allocation-free per harness rules)
__device__ __nv_bfloat16 g_Xhi[(size_t)MAXM * MAXD];
__device__ __nv_bfloat16 g_Xlo[(size_t)MAXM * MAXD];
__device__ __nv_bfloat16 g_Whi[(size_t)MAXD * MAXD];
__device__ __nv_bfloat16 g_Wlo[(size_t)MAXD * MAXD];

// ============================ Prep ============================
__global__ void prep_kernel(const float* __restrict__ weight,
                            const float* __restrict__ a_w,
                            const float* __restrict__ b_w,
                            const float* __restrict__ magnitude,
                            int D_IN, int R) {
    int o = blockIdx.x;
    int tid = threadIdx.x;
    __shared__ float bs[32];
    __shared__ float red[33];
    if (tid < R) bs[tid] = b_w[o * R + tid];
    __syncthreads();

    float wv[8];
    float sumsq = 0.f;
    int cnt = 0;
    for (int d = tid; d < D_IN; d += 256, ++cnt) {
        float corr = 0.f;
        #pragma unroll 16
        for (int r = 0; r < R; ++r) corr += bs[r] * a_w[(size_t)r * D_IN + d];
        float w = weight[(size_t)o * D_IN + d] + SCALING * corr;
        wv[cnt] = w;
        sumsq += w * w;
    }
    #pragma unroll
    for (int off = 16; off; off >>= 1)
        sumsq += __shfl_down_sync(0xffffffffu, sumsq, off);
    if ((tid & 31) == 0) red[tid >> 5] = sumsq;
    __syncthreads();
    if (tid < 32) {
        float v = (tid < 8) ? red[tid] : 0.f;
        #pragma unroll
        for (int off = 16; off; off >>= 1)
            v += __shfl_down_sync(0xffffffffu, v, off);
        if (tid == 0) red[32] = v;
    }
    __syncthreads();
    float scale = magnitude[o] * rsqrtf(red[32]);
    cnt = 0;
    for (int d = tid; d < D_IN; d += 256, ++cnt) {
        float w = wv[cnt] * scale;
        __nv_bfloat16 hi = __float2bfloat16(w);
        __nv_bfloat16 lo = __float2bfloat16(w - __bfloat162float(hi));
        g_Whi[(size_t)o * D_IN + d] = hi;
        g_Wlo[(size_t)o * D_IN + d] = lo;
    }
}

__global__ void split_x_kernel(const float* __restrict__ x, size_t n4) {
    size_t i = (size_t)blockIdx.x * blockDim.x + threadIdx.x;
    size_t stride = (size_t)gridDim.x * blockDim.x;
    const float4* x4 = (const float4*)x;
    __nv_bfloat162* xh2 = (__nv_bfloat162*)g_Xhi;
    __nv_bfloat162* xl2 = (__nv_bfloat162*)g_Xlo;
    for (; i < n4; i += stride) {
        float4 v = x4[i];
        __nv_bfloat16 h0 = __float2bfloat16(v.x);
        __nv_bfloat16 h1 = __float2bfloat16(v.y);
        __nv_bfloat16 h2 = __float2bfloat16(v.z);
        __nv_bfloat16 h3 = __float2bfloat16(v.w);
        __nv_bfloat16 l0 = __float2bfloat16(v.x - __bfloat162float(h0));
        __nv_bfloat16 l1 = __float2bfloat16(v.y - __bfloat162float(h1));
        __nv_bfloat16 l2 = __float2bfloat16(v.z - __bfloat162float(h2));
        __nv_bfloat16 l3 = __float2bfloat16(v.w - __bfloat162float(h3));
        xh2[2 * i]     = __halves2bfloat162(h0, h1);
        xh2[2 * i + 1] = __halves2bfloat162(h2, h3);
        xl2[2 * i]     = __halves2bfloat162(l0, l1);
        xl2[2 * i + 1] = __halves2bfloat162(l2, l3);
    }
}

// ============================ HMMA GEMM (term-fused, 2 CTA/SM) ============================
// out = Xhi@Whi^T + Xlo@Whi^T + Xhi@Wlo^T, fp32 accum.
// CTA tile 128x128, 4 warps (2x2), warp tile 64x64; K-chunk 32; 3-stage
// cp.async pipeline (32KB/stage, 96KB/CTA) -> 2 CTAs per SM so one CTA's
// bar.sync / cp-wait bubbles are filled by the other CTA's mma issue.
#define BM 128
#define BN 128
#define BK 32
#define STAGES 3
#define AT_BYTES (BM * 64)            // 8 KB per A tile
#define BT_BYTES (BN * 64)            // 8 KB per B tile
#define STAGE_BYTES (2 * AT_BYTES + 2 * BT_BYTES)   // 32 KB
#define SMEM_TOTAL (STAGES * STAGE_BYTES)           // 96 KB
#define AHI_OFF 0
#define ALO_OFF AT_BYTES
#define BHI_OFF (2 * AT_BYTES)
#define BLO_OFF (2 * AT_BYTES + BT_BYTES)

__device__ __forceinline__ uint32_t smem_u32(const void* p) {
    uint32_t a;
    asm("{ .reg .u64 t; cvta.to.shared.u64 t, %1; cvt.u32.u64 %0, t; }"
        : "=r"(a) : "l"(p));
    return a;
}
__device__ __forceinline__ void cp16(uint32_t dst, const void* src) {
    asm volatile("cp.async.cg.shared.global [%0], [%1], 16;"
                 :: "r"(dst), "l"(src) : "memory");
}
__device__ __forceinline__ void cp_commit() {
    asm volatile("cp.async.commit_group;" ::: "memory");
}
template <int N_>
__device__ __forceinline__ void cp_wait() {
    asm volatile("cp.async.wait_group %0;" :: "n"(N_) : "memory");
}
__device__ __forceinline__ void ldsm_x4(uint32_t& r0, uint32_t& r1,
                                        uint32_t& r2, uint32_t& r3, uint32_t a) {
    asm volatile("ldmatrix.sync.aligned.m8n8.x4.shared.b16 {%0,%1,%2,%3}, [%4];"
                 : "=r"(r0), "=r"(r1), "=r"(r2), "=r"(r3) : "r"(a));
}
__device__ __forceinline__ void mma16816(float* c, const uint32_t* a,
                                         uint32_t b0, uint32_t b1) {
    asm volatile(
        "mma.sync.aligned.m16n8k16.row.col.f32.bf16.bf16.f32 "
        "{%0,%1,%2,%3}, {%4,%5,%6,%7}, {%8,%9}, {%0,%1,%2,%3};"
        : "+f"(c[0]), "+f"(c[1]), "+f"(c[2]), "+f"(c[3])
        : "r"(a[0]), "r"(a[1]), "r"(a[2]), "r"(a[3]), "r"(b0), "r"(b1));
}
// swizzled byte offset within a tile: row = 4 x 16B chunks, XOR by (row>>1)&3
__device__ __forceinline__ uint32_t sw_off(int row, int ch) {
    return (uint32_t)(row * 64 + ((ch ^ ((row >> 1) & 3)) * 16));
}

__global__ void __launch_bounds__(128, 2)
gemm_hmma_kernel(float* __restrict__ out, int M, int N, int K) {
    extern __shared__ char smem[];
    const uint32_t sb = smem_u32(smem);
    const int tid = threadIdx.x;
    const int wid = tid >> 5;
    const int lane = tid & 31;
    const int wm = (wid & 1) * 64;
    const int wn = (wid >> 1) * 64;
    const int m0 = blockIdx.y * BM;
    const int n0 = blockIdx.x * BN;

    const int nchunk = K / BK;   // 32

    auto issue = [&](int c, int stage) {
        int kofs = c * BK;
        uint32_t base = sb + stage * STAGE_BYTES;
        // A hi/lo: 512 16B units each, 4 per thread (128 threads)
        #pragma unroll
        for (int j = 0; j < 4; ++j) {
            int u = tid + 128 * j;
            int row = u >> 2, ch = u & 3;
            size_t gofs = (size_t)(m0 + row) * K + kofs + ch * 8;
            cp16(base + AHI_OFF + sw_off(row, ch), g_Xhi + gofs);
            cp16(base + ALO_OFF + sw_off(row, ch), g_Xlo + gofs);
        }
        // B hi/lo: 512 16B units each, 4 per thread
        #pragma unroll
        for (int j = 0; j < 4; ++j) {
            int u = tid + 128 * j;
            int row = u >> 2, ch = u & 3;
            size_t gofs = (size_t)(n0 + row) * K + kofs + ch * 8;
            cp16(base + BHI_OFF + sw_off(row, ch), g_Whi + gofs);
            cp16(base + BLO_OFF + sw_off(row, ch), g_Wlo + gofs);
        }
        cp_commit();
    };

    float acc[4][8][4];
    #pragma unroll
    for (int i = 0; i < 4; ++i)
        #pragma unroll
        for (int j = 0; j < 8; ++j)
            #pragma unroll
            for (int q = 0; q < 4; ++q) acc[i][j][q] = 0.f;

    issue(0, 0); issue(1, 1);

    for (int c = 0; c < nchunk; ++c) {
        cp_wait<1>();
        __syncthreads();
        if (c + 2 < nchunk) issue(c + 2, (c + 2) % STAGES);

        uint32_t base = sb + (c % STAGES) * STAGE_BYTES;

        #pragma unroll
        for (int h = 0; h < 2; ++h) {
            const int ch = h * 2 + (lane >> 4);
            uint32_t ah[4][4], al[4][4], bh[4][4], bl[4][4];
            #pragma unroll
            for (int mf = 0; mf < 4; ++mf) {
                int row = wm + mf * 16 + (lane & 15);
                uint32_t so = sw_off(row, ch);
                ldsm_x4(ah[mf][0], ah[mf][1], ah[mf][2], ah[mf][3],
                        base + AHI_OFF + so);
                ldsm_x4(al[mf][0], al[mf][1], al[mf][2], al[mf][3],
                        base + ALO_OFF + so);
            }
            #pragma unroll
            for (int p = 0; p < 4; ++p) {
                int row = wn + p * 16 + (lane & 15);
                uint32_t so = sw_off(row, ch);
                ldsm_x4(bh[p][0], bh[p][1], bh[p][2], bh[p][3],
                        base + BHI_OFF + so);
                ldsm_x4(bl[p][0], bl[p][1], bl[p][2], bl[p][3],
                        base + BLO_OFF + so);
            }
            #pragma unroll
            for (int mf = 0; mf < 4; ++mf)
                #pragma unroll
                for (int p = 0; p < 4; ++p) {
                    mma16816(acc[mf][2 * p],     ah[mf], bh[p][0], bh[p][2]);
                    mma16816(acc[mf][2 * p + 1], ah[mf], bh[p][1], bh[p][3]);
                    mma16816(acc[mf][2 * p],     al[mf], bh[p][0], bh[p][2]);
                    mma16816(acc[mf][2 * p + 1], al[mf], bh[p][1], bh[p][3]);
                    mma16816(acc[mf][2 * p],     ah[mf], bl[p][0], bl[p][2]);
                    mma16816(acc[mf][2 * p + 1], ah[mf], bl[p][1], bl[p][3]);
                }
        }
    }
    cp_wait<0>();

    // Epilogue: direct float2 stores from fragments
    #pragma unroll
    for (int mf = 0; mf < 4; ++mf) {
        int rbase = m0 + wm + mf * 16 + (lane >> 2);
        #pragma unroll
        for (int nf = 0; nf < 8; ++nf) {
            int cbase = n0 + wn + nf * 8 + (lane & 3) * 2;
            float* p0 = out + (size_t)rbase * N + cbase;
            float* p1 = out + (size_t)(rbase + 8) * N + cbase;
            *(float2*)p0 = make_float2(acc[mf][nf][0], acc[mf][nf][1]);
            *(float2*)p1 = make_float2(acc[mf][nf][2], acc[mf][nf][3]);
        }
    }
}

// ============================ launch ============================
extern "C" void kernel_launch(void* const* d_in, const int* in_sizes, int n_in,
                              void* d_out, int out_size) {
    const float* x      = (const float*)d_in[0];
    const float* weight = (const float*)d_in[1];
    const float* a_w    = (const float*)d_in[2];
    const float* b_w    = (const float*)d_in[3];
    const float* mag    = (const float*)d_in[4];
    float* out          = (float*)d_out;

    int D_OUT = in_sizes[4];
    int R     = in_sizes[3] / D_OUT;
    int D_IN  = in_sizes[2] / R;
    int M     = in_sizes[0] / D_IN;

    cudaFuncSetAttribute(gemm_hmma_kernel,
                         cudaFuncAttributeMaxDynamicSharedMemorySize, SMEM_TOTAL);

    prep_kernel<<<D_OUT, 256>>>(weight, a_w, b_w, mag, D_IN, R);
    size_t n4 = ((size_t)M * D_IN) / 4;
    split_x_kernel<<<2048, 256>>>(x, n4);

    dim3 grid(D_OUT / BN, M / BM);
    gemm_hmma_kernel<<<grid, 128, SMEM_TOTAL>>>(out, M, D_OUT, D_IN);
}

// round 7
// speedup vs baseline: 3.2400x; 1.3461x over previous
#include <cuda_runtime.h>
#include <cuda_fp16.h>
#include <stdint.h>
#include <math.h>

#define SCALING 2.0f
#define MAXM 32768
#define MAXD 1024

// Static scratch (allocation-free per harness rules)
__device__ __half g_Xhi[(size_t)MAXM * MAXD];
__device__ __half g_Xlo[(size_t)MAXM * MAXD];
__device__ __half g_Whi[(size_t)MAXD * MAXD];

// ============================ Prep ============================
// w_eff = W[o,:] + 2*b[o,:]@A; scale by mag/||w_eff||; round to fp16.
__global__ void prep_kernel(const float* __restrict__ weight,
                            const float* __restrict__ a_w,
                            const float* __restrict__ b_w,
                            const float* __restrict__ magnitude,
                            int D_IN, int R) {
    int o = blockIdx.x;
    int tid = threadIdx.x;
    __shared__ float bs[32];
    __shared__ float red[33];
    if (tid < R) bs[tid] = b_w[o * R + tid];
    __syncthreads();

    float wv[8];
    float sumsq = 0.f;
    int cnt = 0;
    for (int d = tid; d < D_IN; d += 256, ++cnt) {
        float corr = 0.f;
        #pragma unroll 16
        for (int r = 0; r < R; ++r) corr += bs[r] * a_w[(size_t)r * D_IN + d];
        float w = weight[(size_t)o * D_IN + d] + SCALING * corr;
        wv[cnt] = w;
        sumsq += w * w;
    }
    #pragma unroll
    for (int off = 16; off; off >>= 1)
        sumsq += __shfl_down_sync(0xffffffffu, sumsq, off);
    if ((tid & 31) == 0) red[tid >> 5] = sumsq;
    __syncthreads();
    if (tid < 32) {
        float v = (tid < 8) ? red[tid] : 0.f;
        #pragma unroll
        for (int off = 16; off; off >>= 1)
            v += __shfl_down_sync(0xffffffffu, v, off);
        if (tid == 0) red[32] = v;
    }
    __syncthreads();
    float scale = magnitude[o] * rsqrtf(red[32]);
    cnt = 0;
    for (int d = tid; d < D_IN; d += 256, ++cnt)
        g_Whi[(size_t)o * D_IN + d] = __float2half(wv[cnt] * scale);
}

// Exact two-term fp16 split of X: x = hi + lo (22 mantissa bits preserved).
__global__ void split_x_kernel(const float* __restrict__ x, size_t n4) {
    size_t i = (size_t)blockIdx.x * blockDim.x + threadIdx.x;
    size_t stride = (size_t)gridDim.x * blockDim.x;
    const float4* x4 = (const float4*)x;
    __half2* xh2 = (__half2*)g_Xhi;
    __half2* xl2 = (__half2*)g_Xlo;
    for (; i < n4; i += stride) {
        float4 v = x4[i];
        __half h0 = __float2half(v.x);
        __half h1 = __float2half(v.y);
        __half h2 = __float2half(v.z);
        __half h3 = __float2half(v.w);
        __half l0 = __float2half(v.x - __half2float(h0));
        __half l1 = __float2half(v.y - __half2float(h1));
        __half l2 = __float2half(v.z - __half2float(h2));
        __half l3 = __float2half(v.w - __half2float(h3));
        xh2[2 * i]     = __halves2half2(h0, h1);
        xh2[2 * i + 1] = __halves2half2(h2, h3);
        xl2[2 * i]     = __halves2half2(l0, l1);
        xl2[2 * i + 1] = __halves2half2(l2, l3);
    }
}

// ============================ HMMA GEMM (2-term fp16, chain-free) ============
// out = Xhi@Wh^T + Xlo@Wh^T, fp32 accum. CTA tile 128x128, 4 warps (2x2),
// warp tile 64x64; K-chunk 32; 3-stage cp.async (24KB/stage, 72KB/CTA),
// 2 CTAs/SM. Per term, same-acc mma are 32 issues apart (no RAW chain).
#define BM 128
#define BN 128
#define BK 32
#define STAGES 3
#define AT_BYTES (BM * 64)            // 8 KB per A tile
#define BT_BYTES (BN * 64)            // 8 KB
#define STAGE_BYTES (2 * AT_BYTES + BT_BYTES)   // 24 KB
#define SMEM_TOTAL (STAGES * STAGE_BYTES)       // 72 KB
#define AHI_OFF 0
#define ALO_OFF AT_BYTES
#define BHI_OFF (2 * AT_BYTES)

__device__ __forceinline__ uint32_t smem_u32(const void* p) {
    uint32_t a;
    asm("{ .reg .u64 t; cvta.to.shared.u64 t, %1; cvt.u32.u64 %0, t; }"
        : "=r"(a) : "l"(p));
    return a;
}
__device__ __forceinline__ void cp16(uint32_t dst, const void* src) {
    asm volatile("cp.async.cg.shared.global [%0], [%1], 16;"
                 :: "r"(dst), "l"(src) : "memory");
}
__device__ __forceinline__ void cp_commit() {
    asm volatile("cp.async.commit_group;" ::: "memory");
}
template <int N_>
__device__ __forceinline__ void cp_wait() {
    asm volatile("cp.async.wait_group %0;" :: "n"(N_) : "memory");
}
__device__ __forceinline__ void ldsm_x4(uint32_t& r0, uint32_t& r1,
                                        uint32_t& r2, uint32_t& r3, uint32_t a) {
    asm volatile("ldmatrix.sync.aligned.m8n8.x4.shared.b16 {%0,%1,%2,%3}, [%4];"
                 : "=r"(r0), "=r"(r1), "=r"(r2), "=r"(r3) : "r"(a));
}
__device__ __forceinline__ void mma16816(float* c, const uint32_t* a,
                                         uint32_t b0, uint32_t b1) {
    asm volatile(
        "mma.sync.aligned.m16n8k16.row.col.f32.f16.f16.f32 "
        "{%0,%1,%2,%3}, {%4,%5,%6,%7}, {%8,%9}, {%0,%1,%2,%3};"
        : "+f"(c[0]), "+f"(c[1]), "+f"(c[2]), "+f"(c[3])
        : "r"(a[0]), "r"(a[1]), "r"(a[2]), "r"(a[3]), "r"(b0), "r"(b1));
}
// swizzled byte offset within a tile: row = 4 x 16B chunks, XOR by (row>>1)&3
__device__ __forceinline__ uint32_t sw_off(int row, int ch) {
    return (uint32_t)(row * 64 + ((ch ^ ((row >> 1) & 3)) * 16));
}

__global__ void __launch_bounds__(128, 2)
gemm_hmma_kernel(float* __restrict__ out, int M, int N, int K) {
    extern __shared__ char smem[];
    const uint32_t sb = smem_u32(smem);
    const int tid = threadIdx.x;
    const int wid = tid >> 5;
    const int lane = tid & 31;
    const int wm = (wid & 1) * 64;
    const int wn = (wid >> 1) * 64;
    const int m0 = blockIdx.y * BM;
    const int n0 = blockIdx.x * BN;

    const int nchunk = K / BK;   // 32

    auto issue = [&](int c, int stage) {
        int kofs = c * BK;
        uint32_t base = sb + stage * STAGE_BYTES;
        #pragma unroll
        for (int j = 0; j < 4; ++j) {
            int u = tid + 128 * j;
            int row = u >> 2, ch = u & 3;
            size_t gofs = (size_t)(m0 + row) * K + kofs + ch * 8;
            cp16(base + AHI_OFF + sw_off(row, ch), g_Xhi + gofs);
            cp16(base + ALO_OFF + sw_off(row, ch), g_Xlo + gofs);
        }
        #pragma unroll
        for (int j = 0; j < 4; ++j) {
            int u = tid + 128 * j;
            int row = u >> 2, ch = u & 3;
            size_t gofs = (size_t)(n0 + row) * K + kofs + ch * 8;
            cp16(base + BHI_OFF + sw_off(row, ch), g_Whi + gofs);
        }
        cp_commit();
    };

    float acc[4][8][4];
    #pragma unroll
    for (int i = 0; i < 4; ++i)
        #pragma unroll
        for (int j = 0; j < 8; ++j)
            #pragma unroll
            for (int q = 0; q < 4; ++q) acc[i][j][q] = 0.f;

    issue(0, 0); issue(1, 1);

    for (int c = 0; c < nchunk; ++c) {
        cp_wait<1>();
        __syncthreads();
        if (c + 2 < nchunk) issue(c + 2, (c + 2) % STAGES);

        uint32_t base = sb + (c % STAGES) * STAGE_BYTES;

        #pragma unroll
        for (int h = 0; h < 2; ++h) {
            const int ch = h * 2 + (lane >> 4);
            uint32_t ah[4][4], al[4][4], bh[4][4];
            #pragma unroll
            for (int mf = 0; mf < 4; ++mf) {
                int row = wm + mf * 16 + (lane & 15);
                uint32_t so = sw_off(row, ch);
                ldsm_x4(ah[mf][0], ah[mf][1], ah[mf][2], ah[mf][3],
                        base + AHI_OFF + so);
                ldsm_x4(al[mf][0], al[mf][1], al[mf][2], al[mf][3],
                        base + ALO_OFF + so);
            }
            #pragma unroll
            for (int p = 0; p < 4; ++p) {
                int row = wn + p * 16 + (lane & 15);
                uint32_t so = sw_off(row, ch);
                ldsm_x4(bh[p][0], bh[p][1], bh[p][2], bh[p][3],
                        base + BHI_OFF + so);
            }
            // term 0: hi*w — all 32 mma before any acc is revisited
            #pragma unroll
            for (int mf = 0; mf < 4; ++mf)
                #pragma unroll
                for (int p = 0; p < 4; ++p) {
                    mma16816(acc[mf][2 * p],     ah[mf], bh[p][0], bh[p][2]);
                    mma16816(acc[mf][2 * p + 1], ah[mf], bh[p][1], bh[p][3]);
                }
            // term 1: lo*w — 32 issues after term 0 wrote the same acc
            #pragma unroll
            for (int mf = 0; mf < 4; ++mf)
                #pragma unroll
                for (int p = 0; p < 4; ++p) {
                    mma16816(acc[mf][2 * p],     al[mf], bh[p][0], bh[p][2]);
                    mma16816(acc[mf][2 * p + 1], al[mf], bh[p][1], bh[p][3]);
                }
        }
    }
    cp_wait<0>();

    // Epilogue: direct float2 stores from fragments
    #pragma unroll
    for (int mf = 0; mf < 4; ++mf) {
        int rbase = m0 + wm + mf * 16 + (lane >> 2);
        #pragma unroll
        for (int nf = 0; nf < 8; ++nf) {
            int cbase = n0 + wn + nf * 8 + (lane & 3) * 2;
            float* p0 = out + (size_t)rbase * N + cbase;
            float* p1 = out + (size_t)(rbase + 8) * N + cbase;
            *(float2*)p0 = make_float2(acc[mf][nf][0], acc[mf][nf][1]);
            *(float2*)p1 = make_float2(acc[mf][nf][2], acc[mf][nf][3]);
        }
    }
}

// ============================ launch ============================
extern "C" void kernel_launch(void* const* d_in, const int* in_sizes, int n_in,
                              void* d_out, int out_size) {
    const float* x      = (const float*)d_in[0];
    const float* weight = (const float*)d_in[1];
    const float* a_w    = (const float*)d_in[2];
    const float* b_w    = (const float*)d_in[3];
    const float* mag    = (const float*)d_in[4];
    float* out          = (float*)d_out;

    int D_OUT = in_sizes[4];
    int R     = in_sizes[3] / D_OUT;
    int D_IN  = in_sizes[2] / R;
    int M     = in_sizes[0] / D_IN;

    cudaFuncSetAttribute(gemm_hmma_kernel,
                         cudaFuncAttributeMaxDynamicSharedMemorySize, SMEM_TOTAL);

    prep_kernel<<<D_OUT, 256>>>(weight, a_w, b_w, mag, D_IN, R);
    size_t n4 = ((size_t)M * D_IN) / 4;
    split_x_kernel<<<2048, 256>>>(x, n4);

    dim3 grid(D_OUT / BN, M / BM);
    gemm_hmma_kernel<<<grid, 128, SMEM_TOTAL>>>(out, M, D_OUT, D_IN);
}